// round 16
// baseline (speedup 1.0000x reference)
#include <cuda_runtime.h>
#include <cuda_fp16.h>
#include <cstdint>
#include <math.h>

#define Bn   2
#define Cc   64
#define Hh   224
#define Ww   224
#define HW   (Hh*Ww)
#define NOFF 27
#define COUT 64
#define Jdim 576
#define NCH  9             // chunks == k2 values (k2-major K ordering)
#define TILE 128
#define NT   (HW/TILE)     // 392
#define VSTR 72            // padded k-stride (elems); 144B rows -> LDSM conflict-free
#define OSTR 132           // staging pos-stride

// ---------------- device globals (no allocation allowed) -------------------
__device__ __align__(16) __half g_xt[(size_t)Bn*HW*Cc]; // x transposed fp16: [b][hw][c]
__device__ __align__(16) __half g_wd[NCH][COUT*64];     // deform W fp16 [k2][co][c]
__device__ __align__(16) __half g_wo[NCH][32*64];       // off/mask W fp16 (padded 32 ch)

// ---------------- PTX helpers ------------------------------------------------
__device__ __forceinline__ void mma_f16(float* c, const uint32_t* a,
                                        uint32_t b0, uint32_t b1) {
    asm volatile("mma.sync.aligned.m16n8k16.row.col.f32.f16.f16.f32 "
        "{%0,%1,%2,%3},{%4,%5,%6,%7},{%8,%9},{%0,%1,%2,%3};"
        : "+f"(c[0]), "+f"(c[1]), "+f"(c[2]), "+f"(c[3])
        : "r"(a[0]), "r"(a[1]), "r"(a[2]), "r"(a[3]), "r"(b0), "r"(b1));
}
#define LDSM_X4(r, addr) \
    asm volatile("ldmatrix.sync.aligned.m8n8.x4.shared.b16 {%0,%1,%2,%3}, [%4];" \
        : "=r"((r)[0]), "=r"((r)[1]), "=r"((r)[2]), "=r"((r)[3]) : "r"(addr))

__device__ __forceinline__ uint32_t smem_u32(const void* p) {
    uint32_t a;
    asm("{ .reg .u64 t; cvta.to.shared.u64 t, %1; cvt.u32.u64 %0, t; }" : "=r"(a) : "l"(p));
    return a;
}

// ---------------- transpose x (+ fold in weight prep on b==0 blocks) --------
__global__ void __launch_bounds__(512) transpose_x(
        const float* __restrict__ x,
        const float* __restrict__ w_off,
        const float* __restrict__ w_mask,
        const float* __restrict__ w_def) {
    __shared__ float tile[64][33];
    const int hw0 = blockIdx.x * 32;
    const int b   = blockIdx.y;

    if (b == 0 && blockIdx.x < 108) {
        int idx = blockIdx.x * 512 + threadIdx.x;
        if (idx < NCH*COUT*64) {
            int kc = idx / (COUT*64), r = idx % (COUT*64);
            int co = r >> 6, c = r & 63;
            g_wd[kc][r] = __float2half(w_def[co*Jdim + c*9 + kc]);
        } else {
            int i2 = idx - NCH*COUT*64;
            int kc = i2 / (32*64), r = i2 % (32*64);
            int co = r >> 6, c = r & 63;
            float v = 0.f;
            if (co < 18)      v = w_off[co*Jdim + c*9 + kc];
            else if (co < 27) v = w_mask[(co-18)*Jdim + c*9 + kc];
            g_wo[kc][r] = __float2half(v);
        }
    }

    const int l = threadIdx.x & 31, w = threadIdx.x >> 5;
    const float* xb = x + (size_t)b*Cc*HW;
    #pragma unroll
    for (int i = 0; i < 4; i++) {
        int c = w + 16*i;
        tile[c][l] = xb[(size_t)c*HW + hw0 + l];
    }
    __syncthreads();
    const int c2 = (threadIdx.x & 31) * 2;
    const int hq = threadIdx.x >> 5;
    __half* xt = g_xt + (size_t)b*HW*64;
    #pragma unroll
    for (int i = 0; i < 2; i++) {
        int hw = hq + 16*i;
        __half2 hh = __floats2half2_rn(tile[c2][hw], tile[c2+1][hw]);
        *(__half2*)(xt + (size_t)(hw0 + hw)*64 + c2) = hh;
    }
}

// ============================================================================
// Fused kernel, 256 threads (8 warps): phase A conv -> phase B params
//               -> phase C gather + main GEMM.  128 pos per CTA.
// ============================================================================
#define F_HO  0
#define F_WO  512
#define F_OM  1024                      // float [32][OSTR]      = 16896
#define F_PI  17920                     // int4  [9*128]         = 18432
#define F_PW  36352                     // uint4 half2 weights   = 18432
#define F_V   54784                     // [2buf][128][VSTR] f16 = 36864
#define F_W   91648                     // [2buf][64][VSTR] f16  = 18432
#define F_TOT 110080

__global__ void __launch_bounds__(256, 2) fused_deform(
        const float* __restrict__ b_off,
        const float* __restrict__ b_mask,
        float* __restrict__ out) {
    extern __shared__ char smem[];
    const int tid = threadIdx.x, lane = tid & 31, wid = tid >> 5;  // wid 0..7
    const int hw0 = blockIdx.x * TILE;
    const int b   = blockIdx.y;
    const __half* xt = g_xt + (size_t)b * HW * 64;
    const uint32_t sb = smem_u32(smem);

    int* sHO = (int*)(smem + F_HO);
    int* sWO = (int*)(smem + F_WO);
    if (tid < TILE) {
        int hw = hw0 + tid, ho = hw / Ww;
        sHO[tid] = ho; sWO[tid] = hw - ho*Ww;
    }
    __syncthreads();

    const int q  = lane >> 3;           // 0..3 pos group within warp
    const int c0 = (lane & 7) * 8;      // 8-channel group

    // ======================= PHASE A: offset/mask conv ======================
    {
        auto stageA = [&](int kc, int buf) {
            __half* vh = (__half*)(smem + F_V) + buf*(TILE*VSTR);
            const int ky = kc / 3, kx = kc - ky*3;
            #pragma unroll
            for (int tp = 0; tp < 4; tp++) {
                int pos = (wid << 4) + tp*4 + q;
                int iy = sHO[pos] + ky - 1;
                int ix = sWO[pos] + kx - 1;
                uint4 a = make_uint4(0u, 0u, 0u, 0u);
                if (((unsigned)iy < Hh) && ((unsigned)ix < Ww))
                    a = *(const uint4*)(xt + (size_t)(iy*Ww + ix)*64 + c0);
                *(uint4*)(vh + pos*VSTR + c0) = a;
            }
            const uint32_t* src = (const uint32_t*)(&g_wo[kc][0]);   // 1024 b32
            uint32_t* wd = (uint32_t*)(smem + F_W) + buf*(32*VSTR/2);
            #pragma unroll
            for (int i = 0; i < 4; i++) {
                int idx = tid + i*256;
                int r = idx >> 5, w = idx & 31;
                wd[r*(VSTR/2) + w] = src[idx];
            }
        };

        // 8 warps = 8m x 1n; warp tile 16 pos x 32 co
        const int R = wid * 16;
        const uint32_t aoff  = ((R + (lane & 15))*VSTR + ((lane >> 4) << 3)) * 2;
        const uint32_t boff0 = ((((lane >> 4) << 3) + (lane & 7))*VSTR
                                + (((lane >> 3) & 1) << 3)) * 2;
        const uint32_t boff1 = boff0 + 16*VSTR*2;
        float acc[4][4] = {};

        stageA(0, 0);
        __syncthreads();

        for (int kc = 0; kc < NCH; kc++) {
            int cb = kc & 1;
            if (kc < NCH-1) stageA(kc+1, cb ^ 1);
            uint32_t vB = sb + F_V + cb*(TILE*VSTR*2);
            uint32_t wB = sb + F_W + cb*(32*VSTR*2);
            #pragma unroll
            for (int ks = 0; ks < 4; ks++) {
                uint32_t ah[4], bb0[4], bb1[4];
                LDSM_X4(ah,  vB + aoff  + ks*32);
                LDSM_X4(bb0, wB + boff0 + ks*32);
                LDSM_X4(bb1, wB + boff1 + ks*32);
                mma_f16(acc[0], ah, bb0[0], bb0[1]);
                mma_f16(acc[1], ah, bb0[2], bb0[3]);
                mma_f16(acc[2], ah, bb1[0], bb1[1]);
                mma_f16(acc[3], ah, bb1[2], bb1[3]);
            }
            __syncthreads();
        }

        const int g = lane >> 2, tig = lane & 3;
        float* OM = (float*)(smem + F_OM);
        #pragma unroll
        for (int t = 0; t < 4; t++) {
            int n0 = t*8 + 2*tig;
            OM[(n0    )*OSTR + R+g    ] = acc[t][0];
            OM[(n0 + 1)*OSTR + R+g    ] = acc[t][1];
            OM[(n0    )*OSTR + R+g + 8] = acc[t][2];
            OM[(n0 + 1)*OSTR + R+g + 8] = acc[t][3];
        }
        __syncthreads();
        for (int i = tid; i < NOFF*TILE; i += 256) {
            int co = i >> 7, pos = i & 127;
            float v = OM[co*OSTR + pos] + (co < 18 ? b_off[co] : b_mask[co-18]);
            if (co >= 18) v = 1.f / (1.f + __expf(-v));
            OM[co*OSTR + pos] = v;
        }
        __syncthreads();
    }

    // ======================= PHASE B: bilinear params =======================
    {
        const float* OM = (const float*)(smem + F_OM);
        int4*  pI  = (int4*) (smem + F_PI);
        uint4* pWh = (uint4*)(smem + F_PW);
        for (int i = tid; i < 9*TILE; i += 256) {
            int pos = i & 127;
            int k2  = i >> 7;
            float dy = OM[(2*k2    )*OSTR + pos];
            float dx = OM[(2*k2 + 1)*OSTR + pos];
            float m  = OM[(18 + k2 )*OSTR + pos];
            int ky = k2 / 3, kx = k2 - ky*3;
            float py = dy + (float)(sHO[pos] - 1 + ky);
            float px = dx + (float)(sWO[pos] - 1 + kx);
            float fy = floorf(py), fx = floorf(px);
            float wy1 = py - fy, wx1 = px - fx;
            float wy0 = 1.f - wy1, wx0 = 1.f - wx1;
            int y0 = (int)fy, x0 = (int)fx;
            int y1 = y0 + 1,  x1 = x0 + 1;
            float vy0 = ((unsigned)y0 < Hh) ? 1.f : 0.f;
            float vy1 = ((unsigned)y1 < Hh) ? 1.f : 0.f;
            float vx0 = ((unsigned)x0 < Ww) ? 1.f : 0.f;
            float vx1 = ((unsigned)x1 < Ww) ? 1.f : 0.f;
            int y0c = min(max(y0, 0), Hh-1), y1c = min(max(y1, 0), Hh-1);
            int x0c = min(max(x0, 0), Ww-1), x1c = min(max(x1, 0), Ww-1);
            pI[i] = make_int4(y0c*Ww + x0c, y0c*Ww + x1c,
                              y1c*Ww + x0c, y1c*Ww + x1c);
            __half2 h0 = __float2half2_rn(wy0*wx0*m*vy0*vx0);
            __half2 h1 = __float2half2_rn(wy0*wx1*m*vy0*vx1);
            __half2 h2 = __float2half2_rn(wy1*wx0*m*vy1*vx0);
            __half2 h3 = __float2half2_rn(wy1*wx1*m*vy1*vx1);
            uint4 wp;
            wp.x = *(uint32_t*)&h0; wp.y = *(uint32_t*)&h1;
            wp.z = *(uint32_t*)&h2; wp.w = *(uint32_t*)&h3;
            pWh[i] = wp;
        }
        __syncthreads();
    }

    // ======================= PHASE C: gather + main GEMM ====================
    int4*  pI  = (int4*) (smem + F_PI);
    uint4* pWh = (uint4*)(smem + F_PW);

    auto stageC = [&](int kc, int buf) {
        __half* vh = (__half*)(smem + F_V) + buf*(TILE*VSTR);
        #pragma unroll
        for (int tp = 0; tp < 4; tp++) {
            int pos = (wid << 4) + tp*4 + q;
            int pk = (kc << 7) | pos;
            int4  id = pI[pk];
            uint4 wp = pWh[pk];
            __half2 w0 = *(__half2*)&wp.x, w1 = *(__half2*)&wp.y;
            __half2 w2 = *(__half2*)&wp.z, w3 = *(__half2*)&wp.w;
            uint4 r0 = *(const uint4*)(xt + (size_t)id.x*64 + c0);
            uint4 r1 = *(const uint4*)(xt + (size_t)id.y*64 + c0);
            uint4 r2 = *(const uint4*)(xt + (size_t)id.z*64 + c0);
            uint4 r3 = *(const uint4*)(xt + (size_t)id.w*64 + c0);
            uint4 o;
            #pragma unroll
            for (int j = 0; j < 4; j++) {
                __half2 v = __hmul2(w0, ((__half2*)&r0)[j]);
                v = __hfma2(w1, ((__half2*)&r1)[j], v);
                v = __hfma2(w2, ((__half2*)&r2)[j], v);
                v = __hfma2(w3, ((__half2*)&r3)[j], v);
                ((__half2*)&o)[j] = v;
            }
            *(uint4*)(vh + pos*VSTR + c0) = o;
        }
        const uint32_t* src = (const uint32_t*)(&g_wd[kc][0]);   // 2048 b32
        uint32_t* wd = (uint32_t*)(smem + F_W) + buf*(64*VSTR/2);
        #pragma unroll
        for (int i = 0; i < 8; i++) {
            int idx = tid + i*256;
            int r = idx >> 5, w2i = idx & 31;
            wd[r*(VSTR/2) + w2i] = src[idx];
        }
    };

    // 8 warps = 4m x 2n; warp tile 32 pos x 32 co
    const int R  = (wid >> 1) * 32;
    const int NB = (wid & 1) * 32;
    const uint32_t aoff0 = ((R + (lane & 15))*VSTR + ((lane >> 4) << 3)) * 2;
    const uint32_t aoff1 = aoff0 + 16*VSTR*2;
    const uint32_t boff0 = ((NB + ((lane >> 4) << 3) + (lane & 7))*VSTR
                            + (((lane >> 3) & 1) << 3)) * 2;
    const uint32_t boff1 = boff0 + 16*VSTR*2;
    float acc[2][4][4] = {};

    stageC(0, 0);
    __syncthreads();

    for (int kc = 0; kc < NCH; kc++) {
        int cb = kc & 1;
        if (kc < NCH-1) stageC(kc+1, cb ^ 1);
        uint32_t vB = sb + F_V + cb*(TILE*VSTR*2);
        uint32_t wB = sb + F_W + cb*(64*VSTR*2);
        #pragma unroll
        for (int ks = 0; ks < 4; ks++) {
            uint32_t ah0[4], ah1[4], bb0[4], bb1[4];
            LDSM_X4(ah0, vB + aoff0 + ks*32);
            LDSM_X4(ah1, vB + aoff1 + ks*32);
            LDSM_X4(bb0, wB + boff0 + ks*32);
            LDSM_X4(bb1, wB + boff1 + ks*32);
            mma_f16(acc[0][0], ah0, bb0[0], bb0[1]);
            mma_f16(acc[0][1], ah0, bb0[2], bb0[3]);
            mma_f16(acc[0][2], ah0, bb1[0], bb1[1]);
            mma_f16(acc[0][3], ah0, bb1[2], bb1[3]);
            mma_f16(acc[1][0], ah1, bb0[0], bb0[1]);
            mma_f16(acc[1][1], ah1, bb0[2], bb0[3]);
            mma_f16(acc[1][2], ah1, bb1[0], bb1[1]);
            mma_f16(acc[1][3], ah1, bb1[2], bb1[3]);
        }
        __syncthreads();
    }

    // epilogue: stage [64co][128pos] f32, then coalesced stores
    const int g = lane >> 2, tig = lane & 3;
    float* obuf = (float*)(smem + F_V);
    #pragma unroll
    for (int mi = 0; mi < 2; mi++) {
        #pragma unroll
        for (int ni = 0; ni < 4; ni++) {
            int n0 = NB + ni*8 + 2*tig;
            int po = R + mi*16 + g;
            obuf[(n0    )*OSTR + po    ] = acc[mi][ni][0];
            obuf[(n0 + 1)*OSTR + po    ] = acc[mi][ni][1];
            obuf[(n0    )*OSTR + po + 8] = acc[mi][ni][2];
            obuf[(n0 + 1)*OSTR + po + 8] = acc[mi][ni][3];
        }
    }
    __syncthreads();
    float* ob = out + (size_t)b*COUT*HW + hw0;
    #pragma unroll
    for (int i = tid; i < COUT*32; i += 256) {
        int co = i >> 5, q2 = i & 31;
        float4 v = *(float4*)&obuf[co*OSTR + q2*4];
        *(float4*)&ob[co*HW + q2*4] = v;
    }
}

// ---------------------------------------------------------------------------
extern "C" void kernel_launch(void* const* d_in, const int* in_sizes, int n_in,
                              void* d_out, int out_size) {
    const float* x      = (const float*)d_in[0];
    const float* w_off  = (const float*)d_in[1];
    const float* b_off  = (const float*)d_in[2];
    const float* w_mask = (const float*)d_in[3];
    const float* b_mask = (const float*)d_in[4];
    const float* w_def  = (const float*)d_in[5];
    float* out = (float*)d_out;

    cudaFuncSetAttribute(fused_deform, cudaFuncAttributeMaxDynamicSharedMemorySize, F_TOT);

    transpose_x<<<dim3(HW/32, Bn), 512>>>(x, w_off, w_mask, w_def);
    fused_deform<<<dim3(NT, Bn), 256, F_TOT>>>(b_off, b_mask, out);
}

// round 17
// speedup vs baseline: 1.0911x; 1.0911x over previous
#include <cuda_runtime.h>
#include <cuda_fp16.h>
#include <cstdint>
#include <math.h>

#define Bn   2
#define Cc   64
#define Hh   224
#define Ww   224
#define HW   (Hh*Ww)
#define NOFF 27
#define COUT 64
#define Jdim 576
#define NCH  9             // chunks == k2 values (k2-major K ordering)
#define TILE 128
#define NT   (HW/TILE)     // 392
#define VSTR 72            // padded k-stride (elems); 144B rows -> LDSM conflict-free
#define OSTR 132           // staging pos-stride

// ---------------- device globals (no allocation allowed) -------------------
__device__ __align__(16) __half g_xt[(size_t)Bn*HW*Cc]; // x transposed fp16: [b][hw][c]
__device__ __align__(16) __half g_wd[NCH][COUT*64];     // deform W fp16 [k2][co][c]
__device__ __align__(16) __half g_wo[NCH][32*64];       // off/mask W fp16 (padded 32 ch)

// ---------------- PTX helpers ------------------------------------------------
__device__ __forceinline__ void mma_f16(float* c, const uint32_t* a,
                                        uint32_t b0, uint32_t b1) {
    asm volatile("mma.sync.aligned.m16n8k16.row.col.f32.f16.f16.f32 "
        "{%0,%1,%2,%3},{%4,%5,%6,%7},{%8,%9},{%0,%1,%2,%3};"
        : "+f"(c[0]), "+f"(c[1]), "+f"(c[2]), "+f"(c[3])
        : "r"(a[0]), "r"(a[1]), "r"(a[2]), "r"(a[3]), "r"(b0), "r"(b1));
}
#define LDSM_X4(r, addr) \
    asm volatile("ldmatrix.sync.aligned.m8n8.x4.shared.b16 {%0,%1,%2,%3}, [%4];" \
        : "=r"((r)[0]), "=r"((r)[1]), "=r"((r)[2]), "=r"((r)[3]) : "r"(addr))

__device__ __forceinline__ uint32_t smem_u32(const void* p) {
    uint32_t a;
    asm("{ .reg .u64 t; cvta.to.shared.u64 t, %1; cvt.u32.u64 %0, t; }" : "=r"(a) : "l"(p));
    return a;
}

// ---------------- transpose x (+ fold in weight prep on b==0 blocks) --------
__global__ void __launch_bounds__(512) transpose_x(
        const float* __restrict__ x,
        const float* __restrict__ w_off,
        const float* __restrict__ w_mask,
        const float* __restrict__ w_def) {
    __shared__ float tile[64][33];
    const int hw0 = blockIdx.x * 32;
    const int b   = blockIdx.y;

    if (b == 0 && blockIdx.x < 108) {
        int idx = blockIdx.x * 512 + threadIdx.x;
        if (idx < NCH*COUT*64) {
            int kc = idx / (COUT*64), r = idx % (COUT*64);
            int co = r >> 6, c = r & 63;
            g_wd[kc][r] = __float2half(w_def[co*Jdim + c*9 + kc]);
        } else {
            int i2 = idx - NCH*COUT*64;
            int kc = i2 / (32*64), r = i2 % (32*64);
            int co = r >> 6, c = r & 63;
            float v = 0.f;
            if (co < 18)      v = w_off[co*Jdim + c*9 + kc];
            else if (co < 27) v = w_mask[(co-18)*Jdim + c*9 + kc];
            g_wo[kc][r] = __float2half(v);
        }
    }

    const int l = threadIdx.x & 31, w = threadIdx.x >> 5;
    const float* xb = x + (size_t)b*Cc*HW;
    #pragma unroll
    for (int i = 0; i < 4; i++) {
        int c = w + 16*i;
        tile[c][l] = xb[(size_t)c*HW + hw0 + l];
    }
    __syncthreads();
    const int c2 = (threadIdx.x & 31) * 2;
    const int hq = threadIdx.x >> 5;
    __half* xt = g_xt + (size_t)b*HW*64;
    #pragma unroll
    for (int i = 0; i < 2; i++) {
        int hw = hq + 16*i;
        __half2 hh = __floats2half2_rn(tile[c2][hw], tile[c2+1][hw]);
        *(__half2*)(xt + (size_t)(hw0 + hw)*64 + c2) = hh;
    }
}

// ============================================================================
// Fused kernel, 512 threads: phase A conv (result in smem OM)
//               -> phase C gather (params inline from OM) + main GEMM.
// smem 73.2KB/CTA -> 2 CTAs/SM leaves ~82KB L1D for gather line reuse.
// ============================================================================
#define F_HO  0
#define F_WO  512
#define F_OM  1024                      // float [32][OSTR]      = 16896
#define F_V   17920                     // [2buf][128][VSTR] f16 = 36864
#define F_W   54784                     // [2buf][64][VSTR] f16  = 18432
#define F_TOT 73216

__global__ void __launch_bounds__(512, 2) fused_deform(
        const float* __restrict__ b_off,
        const float* __restrict__ b_mask,
        float* __restrict__ out) {
    extern __shared__ char smem[];
    const int tid = threadIdx.x, lane = tid & 31, wid = tid >> 5;
    const int hw0 = blockIdx.x * TILE;
    const int b   = blockIdx.y;
    const __half* xt = g_xt + (size_t)b * HW * 64;
    const uint32_t sb = smem_u32(smem);

    int* sHO = (int*)(smem + F_HO);
    int* sWO = (int*)(smem + F_WO);
    if (tid < TILE) {
        int hw = hw0 + tid, ho = hw / Ww;
        sHO[tid] = ho; sWO[tid] = hw - ho*Ww;
    }
    __syncthreads();

    const int q  = lane >> 3;           // 0..3 pos group
    const int c0 = (lane & 7) * 8;      // 8-channel group
    float* OM = (float*)(smem + F_OM);

    // ======================= PHASE A: offset/mask conv ======================
    {
        auto stageA = [&](int kc, int buf) {
            __half* vh = (__half*)(smem + F_V) + buf*(TILE*VSTR);
            const int ky = kc / 3, kx = kc - ky*3;
            #pragma unroll
            for (int tp = 0; tp < 2; tp++) {
                int pos = (wid << 3) + tp*4 + q;
                int iy = sHO[pos] + ky - 1;
                int ix = sWO[pos] + kx - 1;
                uint4 a = make_uint4(0u, 0u, 0u, 0u);
                if (((unsigned)iy < Hh) && ((unsigned)ix < Ww))
                    a = *(const uint4*)(xt + (size_t)(iy*Ww + ix)*64 + c0);
                *(uint4*)(vh + pos*VSTR + c0) = a;
            }
            const uint32_t* src = (const uint32_t*)(&g_wo[kc][0]);   // 1024 b32
            uint32_t* wd = (uint32_t*)(smem + F_W) + buf*(32*VSTR/2);
            #pragma unroll
            for (int i = 0; i < 2; i++) {
                int idx = tid + i*512;
                int r = idx >> 5, w = idx & 31;
                wd[r*(VSTR/2) + w] = src[idx];
            }
        };

        const int R  = (wid >> 1) * 16;
        const int NB = (wid & 1) * 16;
        const uint32_t aoff = ((R + (lane & 15))*VSTR + ((lane >> 4) << 3)) * 2;
        const uint32_t boff = ((NB + ((lane >> 4) << 3) + (lane & 7))*VSTR
                               + (((lane >> 3) & 1) << 3)) * 2;
        float acc[2][4] = {};

        stageA(0, 0);
        __syncthreads();

        for (int kc = 0; kc < NCH; kc++) {
            int cb = kc & 1;
            if (kc < NCH-1) stageA(kc+1, cb ^ 1);
            uint32_t vB = sb + F_V + cb*(TILE*VSTR*2);
            uint32_t wB = sb + F_W + cb*(32*VSTR*2);
            #pragma unroll
            for (int ks = 0; ks < 4; ks++) {
                uint32_t ah[4], bb[4];
                LDSM_X4(ah, vB + aoff + ks*32);
                LDSM_X4(bb, wB + boff + ks*32);
                mma_f16(acc[0], ah, bb[0], bb[1]);
                mma_f16(acc[1], ah, bb[2], bb[3]);
            }
            __syncthreads();
        }

        const int g = lane >> 2, tig = lane & 3;
        #pragma unroll
        for (int t = 0; t < 2; t++) {
            int n0 = NB + t*8 + 2*tig;
            OM[(n0    )*OSTR + R+g    ] = acc[t][0];
            OM[(n0 + 1)*OSTR + R+g    ] = acc[t][1];
            OM[(n0    )*OSTR + R+g + 8] = acc[t][2];
            OM[(n0 + 1)*OSTR + R+g + 8] = acc[t][3];
        }
        __syncthreads();
        for (int i = tid; i < NOFF*TILE; i += 512) {
            int co = i >> 7, pos = i & 127;
            float v = OM[co*OSTR + pos] + (co < 18 ? b_off[co] : b_mask[co-18]);
            if (co >= 18) v = 1.f / (1.f + __expf(-v));
            OM[co*OSTR + pos] = v;
        }
        __syncthreads();
    }

    // ======================= PHASE C: gather + main GEMM ====================
    // bilinear params computed inline from smem OM (no precompute arrays)
    auto stageC = [&](int kc, int buf) {
        __half* vh = (__half*)(smem + F_V) + buf*(TILE*VSTR);
        const int ky = kc / 3, kx = kc - ky*3;
        #pragma unroll
        for (int tp = 0; tp < 2; tp++) {
            int pos = (wid << 3) + tp*4 + q;
            float dy = OM[(2*kc    )*OSTR + pos];
            float dx = OM[(2*kc + 1)*OSTR + pos];
            float m  = OM[(18 + kc )*OSTR + pos];
            float py = dy + (float)(sHO[pos] - 1 + ky);
            float px = dx + (float)(sWO[pos] - 1 + kx);
            float fy = floorf(py), fx = floorf(px);
            float wy1 = py - fy, wx1 = px - fx;
            float wy0 = 1.f - wy1, wx0 = 1.f - wx1;
            int y0 = (int)fy, x0 = (int)fx;
            int y1 = y0 + 1,  x1 = x0 + 1;
            float vy0 = ((unsigned)y0 < Hh) ? 1.f : 0.f;
            float vy1 = ((unsigned)y1 < Hh) ? 1.f : 0.f;
            float vx0 = ((unsigned)x0 < Ww) ? 1.f : 0.f;
            float vx1 = ((unsigned)x1 < Ww) ? 1.f : 0.f;
            int y0c = min(max(y0, 0), Hh-1), y1c = min(max(y1, 0), Hh-1);
            int x0c = min(max(x0, 0), Ww-1), x1c = min(max(x1, 0), Ww-1);
            int4 id = make_int4(y0c*Ww + x0c, y0c*Ww + x1c,
                                y1c*Ww + x0c, y1c*Ww + x1c);
            __half2 w0 = __float2half2_rn(wy0*wx0*m*vy0*vx0);
            __half2 w1 = __float2half2_rn(wy0*wx1*m*vy0*vx1);
            __half2 w2 = __float2half2_rn(wy1*wx0*m*vy1*vx0);
            __half2 w3 = __float2half2_rn(wy1*wx1*m*vy1*vx1);
            uint4 r0 = *(const uint4*)(xt + (size_t)id.x*64 + c0);
            uint4 r1 = *(const uint4*)(xt + (size_t)id.y*64 + c0);
            uint4 r2 = *(const uint4*)(xt + (size_t)id.z*64 + c0);
            uint4 r3 = *(const uint4*)(xt + (size_t)id.w*64 + c0);
            uint4 o;
            #pragma unroll
            for (int j = 0; j < 4; j++) {
                __half2 v = __hmul2(w0, ((__half2*)&r0)[j]);
                v = __hfma2(w1, ((__half2*)&r1)[j], v);
                v = __hfma2(w2, ((__half2*)&r2)[j], v);
                v = __hfma2(w3, ((__half2*)&r3)[j], v);
                ((__half2*)&o)[j] = v;
            }
            *(uint4*)(vh + pos*VSTR + c0) = o;
        }
        const uint32_t* src = (const uint32_t*)(&g_wd[kc][0]);   // 2048 b32
        uint32_t* wd = (uint32_t*)(smem + F_W) + buf*(64*VSTR/2);
        #pragma unroll
        for (int i = 0; i < 4; i++) {
            int idx = tid + i*512;
            int r = idx >> 5, w2i = idx & 31;
            wd[r*(VSTR/2) + w2i] = src[idx];
        }
    };

    const int R  = (wid >> 2) * 32;    // 4 m-tiles of 32 pos
    const int NB = (wid & 3) * 16;     // 4 n-tiles of 16 co
    const uint32_t aoff0 = ((R + (lane & 15))*VSTR + ((lane >> 4) << 3)) * 2;
    const uint32_t aoff1 = aoff0 + 16*VSTR*2;
    const uint32_t boff  = ((NB + ((lane >> 4) << 3) + (lane & 7))*VSTR
                            + (((lane >> 3) & 1) << 3)) * 2;
    float acc[2][2][4] = {};

    stageC(0, 0);
    __syncthreads();

    for (int kc = 0; kc < NCH; kc++) {
        int cb = kc & 1;
        if (kc < NCH-1) stageC(kc+1, cb ^ 1);
        uint32_t vB = sb + F_V + cb*(TILE*VSTR*2);
        uint32_t wB = sb + F_W + cb*(64*VSTR*2);
        #pragma unroll
        for (int ks = 0; ks < 4; ks++) {
            uint32_t ah0[4], ah1[4], bb[4];
            LDSM_X4(ah0, vB + aoff0 + ks*32);
            LDSM_X4(ah1, vB + aoff1 + ks*32);
            LDSM_X4(bb,  wB + boff  + ks*32);
            mma_f16(acc[0][0], ah0, bb[0], bb[1]);
            mma_f16(acc[0][1], ah0, bb[2], bb[3]);
            mma_f16(acc[1][0], ah1, bb[0], bb[1]);
            mma_f16(acc[1][1], ah1, bb[2], bb[3]);
        }
        __syncthreads();
    }

    // epilogue: stage [64co][128pos] f32, then coalesced stores
    const int g = lane >> 2, tig = lane & 3;
    float* obuf = (float*)(smem + F_V);
    #pragma unroll
    for (int mi = 0; mi < 2; mi++) {
        #pragma unroll
        for (int ni = 0; ni < 2; ni++) {
            int n0 = NB + ni*8 + 2*tig;
            int po = R + mi*16 + g;
            obuf[(n0    )*OSTR + po    ] = acc[mi][ni][0];
            obuf[(n0 + 1)*OSTR + po    ] = acc[mi][ni][1];
            obuf[(n0    )*OSTR + po + 8] = acc[mi][ni][2];
            obuf[(n0 + 1)*OSTR + po + 8] = acc[mi][ni][3];
        }
    }
    __syncthreads();
    float* ob = out + (size_t)b*COUT*HW + hw0;
    #pragma unroll
    for (int i = tid; i < COUT*32; i += 512) {
        int co = i >> 5, q2 = i & 31;
        float4 v = *(float4*)&obuf[co*OSTR + q2*4];
        *(float4*)&ob[co*HW + q2*4] = v;
    }
}

// ---------------------------------------------------------------------------
extern "C" void kernel_launch(void* const* d_in, const int* in_sizes, int n_in,
                              void* d_out, int out_size) {
    const float* x      = (const float*)d_in[0];
    const float* w_off  = (const float*)d_in[1];
    const float* b_off  = (const float*)d_in[2];
    const float* w_mask = (const float*)d_in[3];
    const float* b_mask = (const float*)d_in[4];
    const float* w_def  = (const float*)d_in[5];
    float* out = (float*)d_out;

    cudaFuncSetAttribute(fused_deform, cudaFuncAttributeMaxDynamicSharedMemorySize, F_TOT);

    transpose_x<<<dim3(HW/32, Bn), 512>>>(x, w_off, w_mask, w_def);
    fused_deform<<<dim3(NT, Bn), 512, F_TOT>>>(b_off, b_mask, out);
}